// round 3
// baseline (speedup 1.0000x reference)
#include <cuda_runtime.h>
#include <math.h>
#include <stdint.h>

#define B_     16
#define T_     2048
#define C_     512
#define G_     2
#define D_     256
#define V_     320
#define N_TOK  (B_*T_)           // 32768
#define NPAIR  (N_TOK*G_)        // 65536
#define GN_N   ((double)(T_*D_)) // 524288

typedef unsigned long long ull;

// ---------------- scratch ----------------------------------------------------
__device__ float  g_y  [N_TOK*C_];
__device__ float  g_ze [N_TOK*C_];
__device__ float  g_zsq[NPAIR];
__device__ ull    g_best[NPAIR];
__device__ double g_p1s[32][16];
__device__ double g_p1q[32][16];
__device__ float  g_mu  [32];
__device__ float  g_rstd[32];
__device__ float  g_esq [G_*V_];
__device__ int    g_hist[G_*V_];
__device__ double g_lpart[8192];

// ---------------- f32x2 helpers ----------------------------------------------
__device__ __forceinline__ ull pack2(float a, float b){
    ull r;
    asm("mov.b64 %0, {%1, %2};"
        : "=l"(r) : "r"(__float_as_uint(a)), "r"(__float_as_uint(b)));
    return r;
}
__device__ __forceinline__ ull fma2(ull a, ull b, ull c){
    ull d;
    asm("fma.rn.f32x2 %0, %1, %2, %3;" : "=l"(d) : "l"(a), "l"(b), "l"(c));
    return d;
}
__device__ __forceinline__ float lo2(ull v){ return __uint_as_float((unsigned)v); }
__device__ __forceinline__ float hi2(ull v){ return __uint_as_float((unsigned)(v >> 32)); }

__device__ __forceinline__ void ld8(const float* __restrict__ p, float* r){
    float4 a = *(const float4*)p;
    float4 b = *(const float4*)(p + 4);
    r[0]=a.x; r[1]=a.y; r[2]=a.z; r[3]=a.w;
    r[4]=b.x; r[5]=b.y; r[6]=b.z; r[7]=b.w;
}

// ---------------- K0: init (g_best, hist, e_sq) ------------------------------
__global__ void k_init(const float* __restrict__ emb){
    int gt = blockIdx.x * blockDim.x + threadIdx.x;
    if (gt < NPAIR) g_best[gt] = 0xFFFFFFFFFFFFFFFFULL;
    if (gt < G_*V_) g_hist[gt] = 0;
    int i = gt - NPAIR;
    if (i >= 0 && i < G_*V_){
        int g = i / V_, v = i % V_;
        const float4* p = (const float4*)(emb + (size_t)v*C_ + g*D_);
        float s = 0.f;
        #pragma unroll 16
        for (int q = 0; q < D_/4; q++){
            float4 e = p[q];
            s += e.x*e.x + e.y*e.y + e.z*e.z + e.w*e.w;
        }
        g_esq[i] = s;
    }
}

// ---------------- K1: grouped GEMM via FFMA2 ---------------------------------
// tile 128 (tokens) x 256 (out), 256 thr, 8x16 per thread (8 f32x2 cols).
__global__ __launch_bounds__(256, 1) void k_gemm1(const float* __restrict__ x,
                                                  const float* __restrict__ w){
    __shared__ float As[16][132];
    __shared__ float Bs[16][260];
    __shared__ double rs[256], rq[256];

    const int tile = blockIdx.x;     // 0..255
    const int g    = blockIdx.y;
    const int tid  = threadIdx.x;
    const int tx   = tid & 15, ty = tid >> 4;
    const int ra   = tid >> 2, ca = (tid & 3) * 4;

    const float* Ag = x + (size_t)tile*128*C_ + g*D_;
    const float* Bg = w + (size_t)g*D_*D_;

    ull acc[8][8];
    #pragma unroll
    for (int i = 0; i < 8; i++)
        #pragma unroll
        for (int j = 0; j < 8; j++) acc[i][j] = 0ull;

    float4 pa[2], pb[4];
    #pragma unroll
    for (int it = 0; it < 2; it++)
        pa[it] = *(const float4*)(Ag + (size_t)(ra + 64*it)*C_ + ca);
    #pragma unroll
    for (int it = 0; it < 4; it++)
        pb[it] = *(const float4*)(Bg + (size_t)(ra + 64*it)*D_ + ca);

    for (int kc = 0; kc < D_; kc += 16){
        #pragma unroll
        for (int it = 0; it < 2; it++){
            int r = ra + 64*it;
            As[ca+0][r] = pa[it].x; As[ca+1][r] = pa[it].y;
            As[ca+2][r] = pa[it].z; As[ca+3][r] = pa[it].w;
        }
        #pragma unroll
        for (int it = 0; it < 4; it++){
            int r = ra + 64*it;
            Bs[ca+0][r] = pb[it].x; Bs[ca+1][r] = pb[it].y;
            Bs[ca+2][r] = pb[it].z; Bs[ca+3][r] = pb[it].w;
        }
        __syncthreads();
        if (kc + 16 < D_){
            #pragma unroll
            for (int it = 0; it < 2; it++)
                pa[it] = *(const float4*)(Ag + (size_t)(ra + 64*it)*C_ + kc + 16 + ca);
            #pragma unroll
            for (int it = 0; it < 4; it++)
                pb[it] = *(const float4*)(Bg + (size_t)(ra + 64*it)*D_ + kc + 16 + ca);
        }
        #pragma unroll
        for (int kk = 0; kk < 16; kk++){
            float av[8];
            *(float4*)(av)     = *(const float4*)&As[kk][ty*4];
            *(float4*)(av + 4) = *(const float4*)&As[kk][64 + ty*4];
            ull ap[8];
            #pragma unroll
            for (int i = 0; i < 8; i++) ap[i] = pack2(av[i], av[i]);
            ull bp[8];
            #pragma unroll
            for (int j = 0; j < 4; j++){
                ulonglong2 t = *(const ulonglong2*)&Bs[kk][64*j + tx*4];
                bp[2*j] = t.x; bp[2*j+1] = t.y;
            }
            #pragma unroll
            for (int i = 0; i < 8; i++)
                #pragma unroll
                for (int j = 0; j < 8; j++)
                    acc[i][j] = fma2(ap[i], bp[j], acc[i][j]);
        }
        __syncthreads();
    }

    // epilogue: store y + block stats
    double s = 0.0, q = 0.0;
    float* Cb = g_y + (size_t)tile*128*C_ + g*D_;
    #pragma unroll
    for (int i = 0; i < 8; i++){
        int m = (i < 4) ? (ty*4 + i) : (64 + ty*4 + (i - 4));
        #pragma unroll
        for (int j = 0; j < 4; j++){
            float4 o = make_float4(lo2(acc[i][2*j]), hi2(acc[i][2*j]),
                                   lo2(acc[i][2*j+1]), hi2(acc[i][2*j+1]));
            s += (double)o.x + (double)o.y + (double)o.z + (double)o.w;
            q += (double)o.x*o.x + (double)o.y*o.y + (double)o.z*o.z + (double)o.w*o.w;
            *(float4*)(Cb + (size_t)m*C_ + 64*j + tx*4) = o;
        }
    }
    rs[tid] = s; rq[tid] = q;
    __syncthreads();
    for (int off = 128; off > 0; off >>= 1){
        if (tid < off){ rs[tid] += rs[tid+off]; rq[tid] += rq[tid+off]; }
        __syncthreads();
    }
    if (tid == 0){
        int b = tile >> 4;
        g_p1s[b*2 + g][tile & 15] = rs[0];
        g_p1q[b*2 + g][tile & 15] = rq[0];
    }
}

// ---------------- K2: finalize groupnorm stats -------------------------------
__global__ void k_stats(){
    int i = threadIdx.x;
    if (i >= 32) return;
    double s = 0.0, q = 0.0;
    for (int j = 0; j < 16; j++){ s += g_p1s[i][j]; q += g_p1q[i][j]; }
    double mu  = s / GN_N;
    double var = q / GN_N - mu*mu;
    g_mu[i]   = (float)mu;
    g_rstd[i] = (float)(1.0 / sqrt(var + 1e-5));
}

// ---------------- K3: normalize + affine -> ze, z_sq -------------------------
__global__ __launch_bounds__(256) void k_norm(const float* __restrict__ gn_w,
                                              const float* __restrict__ gn_b){
    int wg   = (blockIdx.x * 256 + threadIdx.x) >> 5;
    int lane = threadIdx.x & 31;
    int n = wg >> 1, g = wg & 1;
    int b = n >> 11;
    float mu = g_mu[b*G_ + g], rstd = g_rstd[b*G_ + g];
    size_t base = (size_t)n*C_ + g*D_ + lane*8;
    float y[8], ww[8], bb[8], z[8];
    ld8(g_y + base, y);
    ld8(gn_w + g*D_ + lane*8, ww);
    ld8(gn_b + g*D_ + lane*8, bb);
    float s = 0.f;
    #pragma unroll
    for (int i = 0; i < 8; i++){
        z[i] = fmaf((y[i] - mu)*rstd, ww[i], bb[i]);
        s = fmaf(z[i], z[i], s);
    }
    *(float4*)(g_ze + base)     = make_float4(z[0], z[1], z[2], z[3]);
    *(float4*)(g_ze + base + 4) = make_float4(z[4], z[5], z[6], z[7]);
    #pragma unroll
    for (int off = 16; off > 0; off >>= 1) s += __shfl_xor_sync(0xffffffffu, s, off);
    if (lane == 0) g_zsq[wg] = s;
}

// ---------------- K4: VQ GEMM via FFMA2 + packed argmin ----------------------
// tile 128 (tokens) x 160 (codes), 256 thr, 8x10 per thread (5 f32x2 cols).
__global__ __launch_bounds__(256, 1) void k_vq(const float* __restrict__ emb){
    __shared__ float As[16][132];
    __shared__ float Bs[16][164];

    const int tile = blockIdx.x;     // 0..255
    const int nh   = blockIdx.y;     // 0..1 (160 codes each)
    const int g    = blockIdx.z;
    const int tid  = threadIdx.x;
    const int tx   = tid & 15, ty = tid >> 4;
    const int ra   = tid >> 2, ca = (tid & 3) * 4;

    const float* Ag = g_ze + (size_t)tile*128*C_ + g*D_;
    const float* Bg = emb  + (size_t)(nh*160)*C_ + g*D_;

    ull acc[8][5];
    #pragma unroll
    for (int i = 0; i < 8; i++)
        #pragma unroll
        for (int j = 0; j < 5; j++) acc[i][j] = 0ull;

    // B chunk = 160 rows x 16 cols = 640 float4; it=2 valid iff tid<128.
    float4 pa[2], pb[3];
    #pragma unroll
    for (int it = 0; it < 2; it++)
        pa[it] = *(const float4*)(Ag + (size_t)(ra + 64*it)*C_ + ca);
    pb[0] = *(const float4*)(Bg + (size_t)ra*C_ + ca);
    pb[1] = *(const float4*)(Bg + (size_t)(ra + 64)*C_ + ca);
    if (tid < 128)
        pb[2] = *(const float4*)(Bg + (size_t)(ra + 128)*C_ + ca);

    for (int kc = 0; kc < D_; kc += 16){
        #pragma unroll
        for (int it = 0; it < 2; it++){
            int r = ra + 64*it;
            As[ca+0][r] = pa[it].x; As[ca+1][r] = pa[it].y;
            As[ca+2][r] = pa[it].z; As[ca+3][r] = pa[it].w;
        }
        #pragma unroll
        for (int it = 0; it < 3; it++){
            if (it < 2 || tid < 128){
                int r = ra + 64*it;
                Bs[ca+0][r] = pb[it].x; Bs[ca+1][r] = pb[it].y;
                Bs[ca+2][r] = pb[it].z; Bs[ca+3][r] = pb[it].w;
            }
        }
        __syncthreads();
        if (kc + 16 < D_){
            #pragma unroll
            for (int it = 0; it < 2; it++)
                pa[it] = *(const float4*)(Ag + (size_t)(ra + 64*it)*C_ + kc + 16 + ca);
            pb[0] = *(const float4*)(Bg + (size_t)ra*C_ + kc + 16 + ca);
            pb[1] = *(const float4*)(Bg + (size_t)(ra + 64)*C_ + kc + 16 + ca);
            if (tid < 128)
                pb[2] = *(const float4*)(Bg + (size_t)(ra + 128)*C_ + kc + 16 + ca);
        }
        #pragma unroll
        for (int kk = 0; kk < 16; kk++){
            float av[8];
            *(float4*)(av)     = *(const float4*)&As[kk][ty*4];
            *(float4*)(av + 4) = *(const float4*)&As[kk][64 + ty*4];
            ull ap[8];
            #pragma unroll
            for (int i = 0; i < 8; i++) ap[i] = pack2(av[i], av[i]);
            ull bp[5];
            {
                ulonglong2 t0 = *(const ulonglong2*)&Bs[kk][tx*4];
                ulonglong2 t1 = *(const ulonglong2*)&Bs[kk][64 + tx*4];
                bp[0] = t0.x; bp[1] = t0.y; bp[2] = t1.x; bp[3] = t1.y;
                bp[4] = *(const ull*)&Bs[kk][128 + tx*2];
            }
            #pragma unroll
            for (int i = 0; i < 8; i++)
                #pragma unroll
                for (int j = 0; j < 5; j++)
                    acc[i][j] = fma2(ap[i], bp[j], acc[i][j]);
        }
        __syncthreads();
    }

    // epilogue: d2 + packed argmin
    int cols[10];
    cols[0] = tx*4;       cols[1] = tx*4+1;     cols[2] = tx*4+2;     cols[3] = tx*4+3;
    cols[4] = 64+tx*4;    cols[5] = 64+tx*4+1;  cols[6] = 64+tx*4+2;  cols[7] = 64+tx*4+3;
    cols[8] = 128+tx*2;   cols[9] = 128+tx*2+1;
    float eq[10];
    #pragma unroll
    for (int t = 0; t < 10; t++) eq[t] = g_esq[g*V_ + nh*160 + cols[t]];

    #pragma unroll
    for (int i = 0; i < 8; i++){
        int m   = (i < 4) ? (ty*4 + i) : (64 + ty*4 + (i - 4));
        int tok = tile*128 + m;
        float zsq = g_zsq[tok*2 + g];
        float d[10];
        d[0] = lo2(acc[i][0]); d[1] = hi2(acc[i][0]);
        d[2] = lo2(acc[i][1]); d[3] = hi2(acc[i][1]);
        d[4] = lo2(acc[i][2]); d[5] = hi2(acc[i][2]);
        d[6] = lo2(acc[i][3]); d[7] = hi2(acc[i][3]);
        d[8] = lo2(acc[i][4]); d[9] = hi2(acc[i][4]);
        ull best = 0xFFFFFFFFFFFFFFFFULL;
        #pragma unroll
        for (int t = 0; t < 10; t++){
            float d2 = (zsq - 2.0f * d[t]) + eq[t];
            unsigned v = (unsigned)(nh*160 + cols[t]);
            ull p = ((ull)__float_as_uint(d2) << 32) | v;
            best = (p < best) ? p : best;
        }
        #pragma unroll
        for (int off = 1; off < 16; off <<= 1){
            ull o = __shfl_xor_sync(0xffffffffu, best, off);
            best = (o < best) ? o : best;
        }
        if (tx == 0) atomicMin(&g_best[tok*2 + g], best);
    }
}

// ---------------- K5: gather zq, x_out, loss partials, histogram -------------
__global__ __launch_bounds__(256) void k_epi(const float* __restrict__ emb,
                                             float* __restrict__ out){
    __shared__ float warp_s[8];
    int tid  = threadIdx.x;
    int wg   = (blockIdx.x * 256 + tid) >> 5;
    int lane = tid & 31, wl = tid >> 5;
    int n = wg >> 1, g = wg & 1;
    int v = (int)(unsigned)(g_best[wg] & 0xFFFFFFFFULL);

    size_t zb = (size_t)n*C_ + g*D_ + lane*8;
    size_t eb = (size_t)v*C_ + g*D_ + lane*8;
    float ze[8], e[8], r[8];
    ld8(g_ze + zb, ze);
    ld8(emb  + eb, e);
    float s = 0.f;
    #pragma unroll
    for (int i = 0; i < 8; i++){
        float dd = e[i] - ze[i];
        s = fmaf(dd, dd, s);
        r[i] = (e[i] + ze[i]) - ze[i];
    }
    *(float4*)(out + zb)     = make_float4(r[0], r[1], r[2], r[3]);
    *(float4*)(out + zb + 4) = make_float4(r[4], r[5], r[6], r[7]);
    #pragma unroll
    for (int off = 16; off > 0; off >>= 1) s += __shfl_xor_sync(0xffffffffu, s, off);
    if (lane == 0){
        warp_s[wl] = s;
        atomicAdd(&g_hist[g*V_ + v], 1);
        out[(size_t)N_TOK*C_ + wg] = (float)v;
    }
    __syncthreads();
    if (tid == 0){
        double a = 0.0;
        #pragma unroll
        for (int i = 0; i < 8; i++) a += (double)warp_s[i];
        g_lpart[blockIdx.x] = a;
    }
}

// ---------------- K6: final scalars ------------------------------------------
__global__ void k_final(float* __restrict__ out){
    __shared__ double sh[512];
    int t = threadIdx.x;
    double a = 0.0;
    for (int j = t*16; j < t*16 + 16; j++) a += g_lpart[j];
    sh[t] = a; __syncthreads();
    for (int off = 256; off > 0; off >>= 1){
        if (t < off) sh[t] += sh[t+off];
        __syncthreads();
    }
    double S = sh[0];
    __syncthreads();

    double h0 = 0.0, h1 = 0.0;
    if (t < V_){
        double p0 = (double)g_hist[t]      / (double)N_TOK;
        double p1 = (double)g_hist[V_ + t] / (double)N_TOK;
        h0 = p0 * log(p0 + 1e-7);
        h1 = p1 * log(p1 + 1e-7);
    }
    sh[t] = h0; __syncthreads();
    for (int off = 256; off > 0; off >>= 1){
        if (t < off) sh[t] += sh[t+off];
        __syncthreads();
    }
    double H0 = sh[0];
    __syncthreads();
    sh[t] = h1; __syncthreads();
    for (int off = 256; off > 0; off >>= 1){
        if (t < off) sh[t] += sh[t+off];
        __syncthreads();
    }
    double H1 = sh[0];

    if (t == 0){
        double ppl = exp(-H0) + exp(-H1);
        double l   = S / (double)((size_t)N_TOK * C_);
        out[(size_t)N_TOK*C_ + NPAIR]     = (float)ppl;
        out[(size_t)N_TOK*C_ + NPAIR + 1] = (float)(l + 0.25*l);
    }
}

// ---------------- launcher ---------------------------------------------------
extern "C" void kernel_launch(void* const* d_in, const int* in_sizes, int n_in,
                              void* d_out, int out_size){
    const float* x   = (const float*)d_in[0];
    const float* cw  = (const float*)d_in[1];
    const float* gw  = (const float*)d_in[2];
    const float* gb  = (const float*)d_in[3];
    const float* emb = (const float*)d_in[4];
    float* out = (float*)d_out;

    k_init<<<(NPAIR + G_*V_ + 255)/256, 256>>>(emb);

    dim3 g1(256, 2);
    k_gemm1<<<g1, 256>>>(x, cw);

    k_stats<<<1, 32>>>();

    k_norm<<<8192, 256>>>(gw, gb);

    dim3 g4(256, 2, 2);
    k_vq<<<g4, 256>>>(emb);

    k_epi<<<8192, 256>>>(emb, out);

    k_final<<<1, 512>>>(out);
}